// round 9
// baseline (speedup 1.0000x reference)
#include <cuda_runtime.h>
#include <cuda_fp16.h>
#include <cstdint>

// Problem constants
#define T_STEPS   16
#define BATCH     32
#define CHANS     256
#define HW        256
#define KLAG      4
#define TCTX      12
#define SLICE     (BATCH*CHANS*HW)      // 2,097,152
#define N_SPK     (T_STEPS*SLICE)       // 33,554,432
#define OFF_LOSS  (N_SPK)
#define OFF_LSP   (N_SPK + 1)
#define OFF_LSN   (N_SPK + 1 + TCTX*BATCH)
#define INV_CHW   (1.0f / 65536.0f)

// Scratch (device globals)
__device__ unsigned char g_ctx[TCTX * SLICE];            // binary context (t=0..11)
__device__ __half        g_spk16[(size_t)TCTX * SLICE];  // fp16 spk slices t=4..15
__device__ __half        g_w16[CHANS * CHANS];
__device__ float g_dpos[TCTX * BATCH];
__device__ float g_dneg[TCTX * BATCH];
__device__ int   g_inv[BATCH];

// ---------------------------------------------------------------------------
__global__ void init_kernel(const int* __restrict__ rand_idx) {
    int tid = threadIdx.x;
    if (tid < TCTX * BATCH) { g_dpos[tid] = 0.f; g_dneg[tid] = 0.f; }
    if (tid < BATCH) g_inv[rand_idx[tid]] = tid;
}

// Convert W (fp32) -> fp16 once.
__global__ void convw_kernel(const float* __restrict__ Wm) {
    int i = (blockIdx.x * 256 + threadIdx.x) * 4;
    float4 v = *(const float4*)(Wm + i);
    __half2 h01 = __floats2half2_rn(v.x, v.y);
    __half2 h23 = __floats2half2_rn(v.z, v.w);
    uint2 pk;
    pk.x = *(const uint32_t*)&h01;
    pk.y = *(const uint32_t*)&h23;
    *(uint2*)&g_w16[i] = pk;
}

// ---------------------------------------------------------------------------
// Scan + copy: copy spk_rec -> out, leaky scan -> binary ctx (uint8),
// and emit fp16 spk slices for t >= KLAG.
// ---------------------------------------------------------------------------
__global__ __launch_bounds__(256) void scan_copy_kernel(
    const float* __restrict__ spk, float* __restrict__ out)
{
    const int i4 = blockIdx.x * blockDim.x + threadIdx.x;   // 0 .. SLICE/4-1
    const float4* __restrict__ spk4 = (const float4*)spk;
    float4* __restrict__ out4 = (float4*)out;

    float4 mem = make_float4(0.f, 0.f, 0.f, 0.f);

    #pragma unroll
    for (int t = 0; t < T_STEPS; t++) {
        size_t idx = (size_t)t * (SLICE/4) + i4;
        float4 x = spk4[idx];
        out4[idx] = x;
        if (t >= KLAG) {
            __half2 h01 = __floats2half2_rn(x.x, x.y);
            __half2 h23 = __floats2half2_rn(x.z, x.w);
            uint2 pk;
            pk.x = *(const uint32_t*)&h01;
            pk.y = *(const uint32_t*)&h23;
            *(uint2*)&g_spk16[(size_t)(t - KLAG) * SLICE + (size_t)i4 * 4] = pk;
        }
        if (t < TCTX) {
            float r0 = mem.x > 1.f ? 1.f : 0.f;
            float r1 = mem.y > 1.f ? 1.f : 0.f;
            float r2 = mem.z > 1.f ? 1.f : 0.f;
            float r3 = mem.w > 1.f ? 1.f : 0.f;
            mem.x = 0.5f * mem.x + x.x - r0;
            mem.y = 0.5f * mem.y + x.y - r1;
            mem.z = 0.5f * mem.z + x.z - r2;
            mem.w = 0.5f * mem.w + x.w - r3;
            uchar4 s;
            s.x = mem.x > 1.f;
            s.y = mem.y > 1.f;
            s.z = mem.z > 1.f;
            s.w = mem.w > 1.f;
            *(uchar4*)&g_ctx[(size_t)t * SLICE + (size_t)i4 * 4] = s;
        }
    }
}

// ---------------------------------------------------------------------------
// FP16 tensor-core GEMM (m16n8k16 + ldmatrix), cp.async 3-stage pipeline,
// one __syncthreads pair per K-chunk.
// Block tile 128(o) x 256(hw), K=256 in chunks of 16. 8 warps (2x4),
// warp tile 64x64.
// ---------------------------------------------------------------------------
#define KC 16
#define NCHUNK (CHANS / KC)     // 16
#define NSTAGE 3
#define AS_STRIDE 24            // 48B/row = 3 groups: 3r mod 8 distinct
#define BS_STRIDE 264           // 528B/row = 33 groups: 33r mod 8 distinct

__device__ __forceinline__ uint32_t smem_u32(const void* p) {
    return (uint32_t)__cvta_generic_to_shared(p);
}
__device__ __forceinline__ void cp16(uint32_t dst, const void* src) {
    asm volatile("cp.async.cg.shared.global [%0], [%1], 16;" :: "r"(dst), "l"(src));
}
__device__ __forceinline__ void cp_commit() {
    asm volatile("cp.async.commit_group;");
}
template<int N> __device__ __forceinline__ void cp_wait() {
    asm volatile("cp.async.wait_group %0;" :: "n"(N));
}
__device__ __forceinline__ void ldsm_x4(uint32_t* r, uint32_t a) {
    asm volatile("ldmatrix.sync.aligned.m8n8.x4.shared.b16 {%0,%1,%2,%3}, [%4];"
        : "=r"(r[0]), "=r"(r[1]), "=r"(r[2]), "=r"(r[3]) : "r"(a));
}
__device__ __forceinline__ void ldsm_x4_t(uint32_t* r, uint32_t a) {
    asm volatile("ldmatrix.sync.aligned.m8n8.x4.trans.shared.b16 {%0,%1,%2,%3}, [%4];"
        : "=r"(r[0]), "=r"(r[1]), "=r"(r[2]), "=r"(r[3]) : "r"(a));
}
__device__ __forceinline__ void mma_fp16(float* c, const uint32_t* a, const uint32_t* b) {
    asm volatile(
        "mma.sync.aligned.m16n8k16.row.col.f32.f16.f16.f32 "
        "{%0,%1,%2,%3}, {%4,%5,%6,%7}, {%8,%9}, {%0,%1,%2,%3};\n"
        : "+f"(c[0]), "+f"(c[1]), "+f"(c[2]), "+f"(c[3])
        : "r"(a[0]), "r"(a[1]), "r"(a[2]), "r"(a[3]), "r"(b[0]), "r"(b[1]));
}

__global__ __launch_bounds__(256) void gemm_reduce_kernel()
{
    const int p  = blockIdx.x;        // 0..383
    const int tt = p >> 5;            // 0..11
    const int bp = p & 31;            // 0..31
    const int o0 = blockIdx.y * 128;  // 0 or 128

    __shared__ __align__(16) __half As[NSTAGE][128 * AS_STRIDE]; // [st][o][k]
    __shared__ __align__(16) __half Bs[NSTAGE][KC  * BS_STRIDE]; // [st][k][hw]

    const int tid  = threadIdx.x;
    const int wid  = tid >> 5;
    const int lane = tid & 31;
    const int gr   = lane >> 2;
    const int qq   = lane & 3;
    const int wm   = (wid & 1) * 64;   // o offset within block tile
    const int wn   = (wid >> 1) * 64;  // hw offset (0,64,128,192)
    const int lrow = lane & 15;
    const int lcol = (lane >> 4) * 8;

    const __half* __restrict__ Sb = g_spk16 + ((size_t)tt * BATCH + bp) * (CHANS * HW);
    const __half* __restrict__ Wb = g_w16 + (size_t)o0 * CHANS;

    // Fill coords: A = 128x16 fp16 -> 256 16B-chunks (1/thread);
    //              B = 16x256 fp16 -> 512 16B-chunks (2/thread)
    const int a_row = tid >> 1;              // 0..127
    const int a_ch  = (tid & 1) * 8;         // 0,8
    const int b_row = tid >> 4;              // 0..15
    const int b_ch  = (tid & 15) * 8;        // 0..120 (second chunk +128)

    float acc[4][8][4];
    #pragma unroll
    for (int i = 0; i < 4; i++)
        #pragma unroll
        for (int j = 0; j < 8; j++)
            #pragma unroll
            for (int r = 0; r < 4; r++) acc[i][j][r] = 0.f;

    #define FILL_STAGE(c0, st)                                                  \
        do {                                                                    \
            cp16(smem_u32(&As[st][a_row * AS_STRIDE + a_ch]),                   \
                 Wb + (size_t)a_row * CHANS + (c0) + a_ch);                     \
            cp16(smem_u32(&Bs[st][b_row * BS_STRIDE + b_ch]),                   \
                 Sb + (size_t)((c0) + b_row) * HW + b_ch);                      \
            cp16(smem_u32(&Bs[st][b_row * BS_STRIDE + b_ch + 128]),             \
                 Sb + (size_t)((c0) + b_row) * HW + b_ch + 128);                \
            cp_commit();                                                        \
        } while (0)

    FILL_STAGE(0, 0);
    FILL_STAGE(KC, 1);

    #pragma unroll
    for (int c = 0; c < NCHUNK; c++) {
        const int st = c % NSTAGE;
        cp_wait<1>();
        __syncthreads();
        // Refill the buffer consumed at chunk c-1 (safe: sync above)
        if (c + 2 < NCHUNK) {
            FILL_STAGE((c + 2) * KC, (c + 2) % NSTAGE);
        } else {
            cp_commit();   // keep group accounting uniform
        }

        uint32_t af[4][4];
        #pragma unroll
        for (int i = 0; i < 4; i++)
            ldsm_x4(af[i], smem_u32(&As[st][(wm + i * 16 + lrow) * AS_STRIDE + lcol]));
        uint32_t bf[4][4];
        #pragma unroll
        for (int jj = 0; jj < 4; jj++)
            ldsm_x4_t(bf[jj], smem_u32(&Bs[st][lrow * BS_STRIDE + wn + jj * 16 + lcol]));
        #pragma unroll
        for (int i = 0; i < 4; i++)
            #pragma unroll
            for (int j = 0; j < 8; j++)
                mma_fp16(acc[i][j], af[i], &bf[j >> 1][(j & 1) * 2]);
        __syncthreads();
    }

    // Epilogue: reduce fragments against binary ctx slices (pos & neg)
    const int bn = g_inv[bp];
    const unsigned char* __restrict__ cp_ =
        g_ctx + (((size_t)(tt * BATCH + bp) * CHANS + o0) * HW);
    const unsigned char* __restrict__ cn_ =
        g_ctx + (((size_t)(tt * BATCH + bn) * CHANS + o0) * HW);

    float pp = 0.f, pn = 0.f;
    #pragma unroll
    for (int i = 0; i < 4; i++) {
        const int row0 = wm + i * 16 + gr;
        const int row1 = row0 + 8;
        #pragma unroll
        for (int j = 0; j < 8; j++) {
            const int col = wn + j * 8 + qq * 2;
            uchar2 p0 = *(const uchar2*)(cp_ + (size_t)row0 * HW + col);
            uchar2 p1 = *(const uchar2*)(cp_ + (size_t)row1 * HW + col);
            uchar2 n0 = *(const uchar2*)(cn_ + (size_t)row0 * HW + col);
            uchar2 n1 = *(const uchar2*)(cn_ + (size_t)row1 * HW + col);
            pp += acc[i][j][0] * (float)p0.x + acc[i][j][1] * (float)p0.y
                + acc[i][j][2] * (float)p1.x + acc[i][j][3] * (float)p1.y;
            pn += acc[i][j][0] * (float)n0.x + acc[i][j][1] * (float)n0.y
                + acc[i][j][2] * (float)n1.x + acc[i][j][3] * (float)n1.y;
        }
    }

    #pragma unroll
    for (int off = 16; off > 0; off >>= 1) {
        pp += __shfl_xor_sync(0xffffffffu, pp, off);
        pn += __shfl_xor_sync(0xffffffffu, pn, off);
    }
    if (lane == 0) {
        atomicAdd(&g_dpos[tt * BATCH + bp], pp);
        atomicAdd(&g_dneg[tt * BATCH + bn], pn);
    }
}

// ---------------------------------------------------------------------------
__global__ void finalize_kernel(float* __restrict__ out) {
    __shared__ float shneg[TCTX * BATCH];
    __shared__ float shlsn[TCTX];
    __shared__ float shsum[TCTX * BATCH];
    const int tid = threadIdx.x;   // 0..383

    float lsp = logf(expf(g_dpos[tid] * INV_CHW) + 1e-4f);
    out[OFF_LSP + tid] = lsp;
    shneg[tid] = expf(g_dneg[tid] * INV_CHW) + 1e-4f;
    __syncthreads();

    if (tid < TCTX) {
        float s = 0.f;
        #pragma unroll
        for (int b = 0; b < BATCH; b++) s += shneg[tid * BATCH + b];
        float lsn = logf(s);
        shlsn[tid] = lsn;
        out[OFF_LSN + tid] = lsn;
    }
    __syncthreads();

    shsum[tid] = shlsn[tid >> 5] - lsp;
    __syncthreads();
    if (tid < 128) shsum[tid] = shsum[tid] + shsum[tid + 128] + shsum[tid + 256];
    __syncthreads();
    for (int off = 64; off > 0; off >>= 1) {
        if (tid < off) shsum[tid] += shsum[tid + off];
        __syncthreads();
    }
    if (tid == 0) out[OFF_LOSS] = shsum[0] * (1.0f / (TCTX * BATCH));
}

// ---------------------------------------------------------------------------
extern "C" void kernel_launch(void* const* d_in, const int* in_sizes, int n_in,
                              void* d_out, int out_size) {
    const float* spk  = (const float*)d_in[0];
    const float* Wm   = (const float*)d_in[2];
    const int*   ridx = (const int*)d_in[3];
    float* out = (float*)d_out;

    init_kernel<<<1, 384>>>(ridx);
    convw_kernel<<<64, 256>>>(Wm);
    scan_copy_kernel<<<SLICE / 4 / 256, 256>>>(spk, out);
    gemm_reduce_kernel<<<dim3(TCTX * BATCH, 2), 256>>>();
    finalize_kernel<<<1, 384>>>(out);
}